// round 4
// baseline (speedup 1.0000x reference)
#include <cuda_runtime.h>
#include <cuda_bf16.h>
#include <cstdint>

// Problem constants
#define BATCH 8192
#define D_IN  1024
#define NH    2048
#define KLR   4
#define NCLS  1000
#define BN_EPS 1e-5f
#define NSEG  32

#define STAGES 4
#define STAGE_BYTES 49152           // A 16KB (128x128B) | B 32KB (256x128B)
#define SMEM_TOTAL (STAGES * STAGE_BYTES)

static __device__ __forceinline__ uint32_t smem_u32(const void* p) {
    uint32_t a;
    asm("{ .reg .u64 t; cvta.to.shared.u64 t, %1; cvt.u32.u64 %0, t; }" : "=r"(a) : "l"(p));
    return a;
}
static __device__ __forceinline__ void cp16(uint32_t dst, const void* src, uint32_t bytes) {
    asm volatile("cp.async.cg.shared.global [%0], [%1], 16, %2;" :: "r"(dst), "l"(src), "r"(bytes) : "memory");
}
#define CP_COMMIT() asm volatile("cp.async.commit_group;" ::: "memory")
#define CP_WAIT(n)  asm volatile("cp.async.wait_group %0;" :: "n"(n) : "memory")
#define LDSM4(r0, r1, r2, r3, a) \
    asm volatile("ldmatrix.sync.aligned.m8n8.x4.shared.b16 {%0,%1,%2,%3}, [%4];" \
        : "=r"(r0), "=r"(r1), "=r"(r2), "=r"(r3) : "r"(a))
#define MMA16816(c, a, b0, b1) \
    asm volatile("mma.sync.aligned.m16n8k16.row.col.f32.bf16.bf16.f32 " \
        "{%0,%1,%2,%3},{%4,%5,%6,%7},{%8,%9},{%0,%1,%2,%3};" \
        : "+f"((c)[0]), "+f"((c)[1]), "+f"((c)[2]), "+f"((c)[3]) \
        : "r"((a)[0]), "r"((a)[1]), "r"((a)[2]), "r"((a)[3]), "r"(b0), "r"(b1))

// ---------------- static device scratch ----------------
__device__ float g_S[(size_t)BATCH * NH];
__device__ float g_P[(size_t)BATCH * NH * KLR];
__device__ float g_t[(size_t)BATCH * NH];
__device__ float g_feat[(size_t)BATCH * NH];
__device__ __align__(1024) __nv_bfloat16 g_a2x[(size_t)BATCH * 2 * D_IN];    // x   [hi|lo]
__device__ __align__(1024) __nv_bfloat16 g_a2f[(size_t)BATCH * 2 * NH];      // feat [hi|lo]
__device__ __align__(1024) __nv_bfloat16 g_b2mu[(size_t)NH * 2 * NH];        // mu  [hi|lo]
__device__ __align__(1024) __nv_bfloat16 g_b2v[(size_t)(NH * KLR) * 2 * NH]; // v   [hi|lo]
__device__ __align__(1024) __nv_bfloat16 g_b2l[(size_t)NCLS * 2 * NH];       // Wl  [hi|lo]
__device__ float g_rowsq[BATCH];
__device__ float g_msq[NH];
__device__ float g_c[NH * KLR];
__device__ float g_mean[NH];
__device__ float g_scale[NH];
__device__ float g_shift[NH];
__device__ float g_psum[NSEG * NH];
__device__ float g_psq[NSEG * NH];

// ================= HMMA bf16 split GEMM (128x256 tile) =================
// Logical C[m,n] = sum over 3 segments: hiA*hiB + loA*hiB + hiA*loB.
// Physical storage: A2 (M, 2*Kd) = [hi|lo], B2 (N, 2*Kd) = [hi|lo].
// Chunk remap: i in [0,3*nk1): A uses phys chunk (i>=2*nk1 ? i-2*nk1 : i),
//                              B uses phys chunk (i>=nk1   ? i-nk1   : i).
__global__ void __launch_bounds__(256)
gemm_mma(const __nv_bfloat16* __restrict__ A2, const __nv_bfloat16* __restrict__ B2,
         float* __restrict__ C, int Mt, int N, int Kd, const float* __restrict__ bias)
{
    extern __shared__ __align__(1024) char smem[];
    const uint32_t sbase = smem_u32(smem);
    const int tid = threadIdx.x;
    const int wid = tid >> 5;
    const int lane = tid & 31;
    const int wm = wid >> 2;          // 0..1  (m-warp, 64 rows)
    const int wn = wid & 3;           // 0..3  (n-warp, 64 cols)

    // m-fast raster: consecutive CTAs share the B tile; A cycles within L2
    const int mtile = blockIdx.x % Mt;
    const int ntile = blockIdx.x / Mt;
    const int row0 = mtile * 128;
    const int col0 = ntile * 256;
    const int nk1 = Kd >> 6;
    const int nk = 3 * nk1;
    const int Kd2 = 2 * Kd;

    float acc[4][8][4];
#pragma unroll
    for (int i = 0; i < 4; i++)
#pragma unroll
        for (int j = 0; j < 8; j++)
#pragma unroll
            for (int r = 0; r < 4; r++) acc[i][j][r] = 0.f;

    // ldmatrix lane geometry
    const int aRow = wm * 64 + (lane & 15);
    const int aK8 = (lane >> 4) * 8;
    const int bRowBase = wn * 64 + (lane & 7) + ((lane >> 4) & 1) * 8;
    const int bK8 = ((lane >> 3) & 1) * 8;

    auto issue = [&](int i) {
        if (i < nk) {
            const int s = i & 3;
            const uint32_t stA = sbase + s * STAGE_BYTES;
            const uint32_t stB = stA + 16384;
            const int ia = (i >= 2 * nk1) ? i - 2 * nk1 : i;
            const int ib = (i >= nk1) ? i - nk1 : i;
            const __nv_bfloat16* Ab = A2 + (size_t)row0 * Kd2 + (ia << 6);
            const __nv_bfloat16* Bb = B2 + (ib << 6);
#pragma unroll
            for (int it = 0; it < 4; it++) {
                int id = it * 256 + tid;
                int row = id >> 3, c = id & 7;
                uint32_t off = (uint32_t)(row * 128 + ((c * 16) ^ ((row & 7) << 4)));
                cp16(stA + off, Ab + (size_t)row * Kd2 + c * 8, 16);
            }
#pragma unroll
            for (int it = 0; it < 8; it++) {
                int id = it * 256 + tid;
                int row = id >> 3, c = id & 7;
                int gn = col0 + row;
                uint32_t bytes = (gn < N) ? 16u : 0u;
                if (gn >= N) gn = col0;
                uint32_t off = (uint32_t)(row * 128 + ((c * 16) ^ ((row & 7) << 4)));
                cp16(stB + off, Bb + (size_t)gn * Kd2 + c * 8, bytes);
            }
        }
        CP_COMMIT();
    };

#pragma unroll
    for (int i = 0; i < STAGES - 1; i++) issue(i);

    for (int i = 0; i < nk; i++) {
        CP_WAIT(STAGES - 2);
        __syncthreads();
        const int s = i & 3;
        const uint32_t stA = sbase + s * STAGE_BYTES;
        const uint32_t stB = stA + 16384;
#pragma unroll
        for (int ks = 0; ks < 4; ks++) {
            uint32_t a[4][4], b[4][4];
            const int kc = ks * 16;
#pragma unroll
            for (int mi = 0; mi < 4; mi++) {
                int row = aRow + mi * 16;
                uint32_t off = (uint32_t)(row * 128 + (((kc + aK8) * 2) ^ ((row & 7) << 4)));
                LDSM4(a[mi][0], a[mi][1], a[mi][2], a[mi][3], stA + off);
            }
#pragma unroll
            for (int nb = 0; nb < 4; nb++) {
                int row = bRowBase + nb * 16;
                uint32_t off = (uint32_t)(row * 128 + (((kc + bK8) * 2) ^ ((row & 7) << 4)));
                LDSM4(b[nb][0], b[nb][1], b[nb][2], b[nb][3], stB + off);
            }
#pragma unroll
            for (int mi = 0; mi < 4; mi++)
#pragma unroll
                for (int ni = 0; ni < 8; ni++)
                    MMA16816(acc[mi][ni], a[mi], b[ni >> 1][(ni & 1) * 2], b[ni >> 1][(ni & 1) * 2 + 1]);
        }
        issue(i + STAGES - 1);
    }

    // ---- epilogue ----
#pragma unroll
    for (int mi = 0; mi < 4; mi++) {
        const int m = row0 + wm * 64 + mi * 16 + (lane >> 2);
#pragma unroll
        for (int ni = 0; ni < 8; ni++) {
            const int col = col0 + wn * 64 + ni * 8 + (lane & 3) * 2;
            if (col < N) {
                float b0 = 0.f, b1 = 0.f;
                if (bias) { b0 = bias[col]; b1 = bias[col + 1]; }
                float2 v0 = make_float2(acc[mi][ni][0] + b0, acc[mi][ni][1] + b1);
                float2 v1 = make_float2(acc[mi][ni][2] + b0, acc[mi][ni][3] + b1);
                *(float2*)(C + (size_t)m * N + col) = v0;
                *(float2*)(C + (size_t)(m + 8) * N + col) = v1;
            }
        }
    }
}

// ---------------- split: fp32 -> [hi | lo] bf16 per row ----------------
__global__ void split2(const float* __restrict__ src, __nv_bfloat16* __restrict__ dst, int D) {
    size_t i = (size_t)blockIdx.x * 256 + threadIdx.x;
    size_t r = i / (size_t)D;
    int d = (int)(i - r * D);
    float x = src[i];
    __nv_bfloat16 h = __float2bfloat16(x);
    __nv_bfloat16 l = __float2bfloat16(x - __bfloat162float(h));
    __nv_bfloat16* o = dst + r * (size_t)(2 * D);
    o[d] = h; o[D + d] = l;
}

// ---------------- row sum of squares ----------------
__global__ void rowsq_kernel(const float* __restrict__ x, float* __restrict__ out, int D) {
    int b = blockIdx.x;
    const float* p = x + (size_t)b * D;
    float s = 0.f;
    for (int i = threadIdx.x; i < D; i += 256) { float v = p[i]; s = fmaf(v, v, s); }
    __shared__ float red[256];
    red[threadIdx.x] = s;
    __syncthreads();
    for (int off = 128; off > 0; off >>= 1) {
        if (threadIdx.x < off) red[threadIdx.x] += red[threadIdx.x + off];
        __syncthreads();
    }
    if (threadIdx.x == 0) out[b] = red[0];
}

// ---------------- per-n constants: msq, c ----------------
__global__ void prep_kernel(const float* __restrict__ mu, const float* __restrict__ v,
                            float* __restrict__ msq, float* __restrict__ c, int D) {
    int n = blockIdx.x;
    const float* mp = mu + (size_t)n * D;
    const float* vp = v + (size_t)n * KLR * D;
    float acc[5] = {0.f, 0.f, 0.f, 0.f, 0.f};
    for (int i = threadIdx.x; i < D; i += 256) {
        float m = mp[i];
        acc[0] = fmaf(m, m, acc[0]);
        acc[1] = fmaf(m, vp[i], acc[1]);
        acc[2] = fmaf(m, vp[(size_t)D + i], acc[2]);
        acc[3] = fmaf(m, vp[(size_t)2 * D + i], acc[3]);
        acc[4] = fmaf(m, vp[(size_t)3 * D + i], acc[4]);
    }
    __shared__ float red[256];
    for (int j = 0; j < 5; j++) {
        red[threadIdx.x] = acc[j];
        __syncthreads();
        for (int off = 128; off > 0; off >>= 1) {
            if (threadIdx.x < off) red[threadIdx.x] += red[threadIdx.x + off];
            __syncthreads();
        }
        if (threadIdx.x == 0) {
            if (j == 0) msq[n] = red[0];
            else        c[n * KLR + (j - 1)] = red[0];
        }
        __syncthreads();
    }
}

// ---------------- fused quad epilogue + BN partial sum ----------------
// grid (NH/256, NSEG); thread owns one column n, loops over 256 rows of its segment.
__global__ void quad_bnsum(const float* __restrict__ S, const float* __restrict__ P,
                           const float* __restrict__ rsq, const float* __restrict__ msq,
                           const float* __restrict__ c, const float* __restrict__ lam,
                           float* __restrict__ t, float* __restrict__ psum, int mode) {
    int n = blockIdx.x * 256 + threadIdx.x;
    int seg = blockIdx.y;
    const int rows = BATCH / NSEG;
    float lamn = lam[n];
    float msqn = msq[n];
    float4 cc = *(const float4*)(c + n * 4);
    float s = 0.f;
    size_t b0 = (size_t)seg * rows;
    for (int r = 0; r < rows; r++) {
        size_t b = b0 + r;
        size_t idx = b * NH + n;
        float q = lamn * (rsq[b] - 2.f * S[idx] + msqn);
        float4 p = *(const float4*)(P + idx * 4);
        float d0 = p.x - cc.x, d1 = p.y - cc.y, d2 = p.z - cc.z, d3 = p.w - cc.w;
        q += d0 * d0 + d1 * d1 + d2 * d2 + d3 * d3;
        float v = mode ? expf(-q * (1.0f / (float)NH)) : -q;
        t[idx] = v;
        s += v;
    }
    psum[seg * NH + n] = s;
}

// ---------------- BatchNorm (two-pass variance) ----------------
__global__ void bn_mean(const float* __restrict__ psum, float* __restrict__ mean) {
    int n = blockIdx.x * 256 + threadIdx.x;
    float s = 0.f;
    for (int i = 0; i < NSEG; i++) s += psum[i * NH + n];
    mean[n] = s * (1.0f / (float)BATCH);
}
__global__ void bn_var_partial(const float* __restrict__ t, const float* __restrict__ mean,
                               float* __restrict__ psq) {
    int n = blockIdx.x * 256 + threadIdx.x;
    int seg = blockIdx.y;
    const int rows = BATCH / NSEG;
    const float* p = t + (size_t)seg * rows * NH + n;
    float m = mean[n];
    float s = 0.f;
    for (int r = 0; r < rows; r++) { float d = p[(size_t)r * NH] - m; s = fmaf(d, d, s); }
    psq[seg * NH + n] = s;
}
__global__ void bn_finalize(const float* __restrict__ psq, const float* __restrict__ mean,
                            const float* __restrict__ g, const float* __restrict__ be,
                            float* __restrict__ scale, float* __restrict__ shift) {
    int n = blockIdx.x * 256 + threadIdx.x;
    float s = 0.f;
    for (int i = 0; i < NSEG; i++) s += psq[i * NH + n];
    float var = s * (1.0f / (float)BATCH);
    float rstd = rsqrtf(var + BN_EPS);
    float sc = g[n] * rstd;
    scale[n] = sc;
    shift[n] = be[n] - mean[n] * sc;
}
// applies BN (+optional relu), writes float feat AND [hi|lo] bf16 pair rows
__global__ void bn_apply(const float* __restrict__ t, const float* __restrict__ scale,
                         const float* __restrict__ shift, float* __restrict__ feat,
                         __nv_bfloat16* __restrict__ f2,
                         float* o1, float* o2, int relu) {
    size_t idx = (size_t)blockIdx.x * 256 + threadIdx.x;
    int n = (int)(idx & (NH - 1));
    size_t b = idx >> 11;
    float v = fmaf(t[idx], scale[n], shift[n]);
    if (relu) v = fmaxf(v, 0.f);
    feat[idx] = v;
    __nv_bfloat16 h = __float2bfloat16(v);
    __nv_bfloat16 l = __float2bfloat16(v - __bfloat162float(h));
    __nv_bfloat16* o = f2 + b * (size_t)(2 * NH);
    o[n] = h; o[NH + n] = l;
    if (o1) o1[idx] = v;
    if (o2) o2[idx] = v;
}

// ---------------- host orchestration ----------------
extern "C" void kernel_launch(void* const* d_in, const int* in_sizes, int n_in,
                              void* d_out, int out_size) {
    const float* x    = (const float*)d_in[0];
    const float* mu1  = (const float*)d_in[1];
    const float* lam1 = (const float*)d_in[2];
    const float* v1   = (const float*)d_in[3];
    const float* g1   = (const float*)d_in[4];
    const float* b1   = (const float*)d_in[5];
    const float* mu2  = (const float*)d_in[6];
    const float* lam2 = (const float*)d_in[7];
    const float* v2   = (const float*)d_in[8];
    const float* g2   = (const float*)d_in[9];
    const float* b2   = (const float*)d_in[10];
    const float* Wl   = (const float*)d_in[11];
    const float* bl   = (const float*)d_in[12];

    float *pS, *pP, *pT, *pF, *pR, *pM, *pC, *pMean, *pScale, *pShift, *pPsum, *pPsq;
    __nv_bfloat16 *pA2x, *pA2f, *pB2mu, *pB2v, *pB2l;
    cudaGetSymbolAddress((void**)&pS, g_S);
    cudaGetSymbolAddress((void**)&pP, g_P);
    cudaGetSymbolAddress((void**)&pT, g_t);
    cudaGetSymbolAddress((void**)&pF, g_feat);
    cudaGetSymbolAddress((void**)&pA2x, g_a2x);
    cudaGetSymbolAddress((void**)&pA2f, g_a2f);
    cudaGetSymbolAddress((void**)&pB2mu, g_b2mu);
    cudaGetSymbolAddress((void**)&pB2v, g_b2v);
    cudaGetSymbolAddress((void**)&pB2l, g_b2l);
    cudaGetSymbolAddress((void**)&pR, g_rowsq);
    cudaGetSymbolAddress((void**)&pM, g_msq);
    cudaGetSymbolAddress((void**)&pC, g_c);
    cudaGetSymbolAddress((void**)&pMean, g_mean);
    cudaGetSymbolAddress((void**)&pScale, g_scale);
    cudaGetSymbolAddress((void**)&pShift, g_shift);
    cudaGetSymbolAddress((void**)&pPsum, g_psum);
    cudaGetSymbolAddress((void**)&pPsq, g_psq);

    cudaFuncSetAttribute(gemm_mma, cudaFuncAttributeMaxDynamicSharedMemorySize, SMEM_TOTAL);

    const size_t LOGITS_SZ = (size_t)BATCH * NCLS;
    const size_t FEAT_SZ   = (size_t)BATCH * NH;
    float* out = (float*)d_out;
    size_t extra = ((size_t)out_size > LOGITS_SZ) ? ((size_t)out_size - LOGITS_SZ) / FEAT_SZ : 0;
    float* f1dst = (extra >= 1) ? out + LOGITS_SZ : nullptr;
    float* f2a   = (extra >= 2) ? out + LOGITS_SZ + FEAT_SZ : nullptr;
    float* f2b   = (extra >= 3) ? out + LOGITS_SZ + 2 * FEAT_SZ : nullptr;

    dim3 bn_grid(NH / 256, NSEG);
    const int elem_blocks = (int)(((size_t)BATCH * NH) / 256);
    const int Mt = BATCH / 128;   // 64

    // ---------- Layer 1 ----------
    split2<<<(BATCH * D_IN) / 256, 256>>>(x, pA2x, D_IN);
    split2<<<(NH * D_IN) / 256, 256>>>(mu1, pB2mu, D_IN);
    split2<<<(NH * KLR * D_IN) / 256, 256>>>(v1, pB2v, D_IN);
    rowsq_kernel<<<BATCH, 256>>>(x, pR, D_IN);
    prep_kernel<<<NH, 256>>>(mu1, v1, pM, pC, D_IN);
    gemm_mma<<<Mt * (NH / 256), 256, SMEM_TOTAL>>>(pA2x, pB2mu, pS, Mt, NH, D_IN, nullptr);
    gemm_mma<<<Mt * ((NH * KLR) / 256), 256, SMEM_TOTAL>>>(pA2x, pB2v, pP, Mt, NH * KLR, D_IN, nullptr);
    quad_bnsum<<<bn_grid, 256>>>(pS, pP, pR, pM, pC, lam1, pT, pPsum, 0);
    bn_mean<<<NH / 256, 256>>>(pPsum, pMean);
    bn_var_partial<<<bn_grid, 256>>>(pT, pMean, pPsq);
    bn_finalize<<<NH / 256, 256>>>(pPsq, pMean, g1, b1, pScale, pShift);
    bn_apply<<<elem_blocks, 256>>>(pT, pScale, pShift, pF, pA2f, f1dst, nullptr, 0);

    // ---------- Layer 2 ----------
    split2<<<(NH * NH) / 256, 256>>>(mu2, pB2mu, NH);
    split2<<<(NH * KLR * NH) / 256, 256>>>(v2, pB2v, NH);
    rowsq_kernel<<<BATCH, 256>>>(pF, pR, NH);
    prep_kernel<<<NH, 256>>>(mu2, v2, pM, pC, NH);
    gemm_mma<<<Mt * (NH / 256), 256, SMEM_TOTAL>>>(pA2f, pB2mu, pS, Mt, NH, NH, nullptr);
    gemm_mma<<<Mt * ((NH * KLR) / 256), 256, SMEM_TOTAL>>>(pA2f, pB2v, pP, Mt, NH * KLR, NH, nullptr);
    quad_bnsum<<<bn_grid, 256>>>(pS, pP, pR, pM, pC, lam2, pT, pPsum, 1);
    bn_mean<<<NH / 256, 256>>>(pPsum, pMean);
    bn_var_partial<<<bn_grid, 256>>>(pT, pMean, pPsq);
    bn_finalize<<<NH / 256, 256>>>(pPsq, pMean, g2, b2, pScale, pShift);
    bn_apply<<<elem_blocks, 256>>>(pT, pScale, pShift, pF, pA2f, f2a, f2b, 1);

    // ---------- Logits ----------
    split2<<<(NCLS * NH) / 256, 256>>>(Wl, pB2l, NH);
    gemm_mma<<<Mt * ((NCLS + 255) / 256), 256, SMEM_TOTAL>>>(pA2f, pB2l, out, Mt, NCLS, NH, bl);
}

// round 5
// speedup vs baseline: 1.0996x; 1.0996x over previous
#include <cuda_runtime.h>
#include <cuda_bf16.h>
#include <cstdint>

// Problem constants
#define BATCH 8192
#define D_IN  1024
#define NH    2048
#define KLR   4
#define NCLS  1000
#define BN_EPS 1e-5f
#define NSEG  32

#define STAGES 3
#define STAGE_BYTES 32768           // A 16KB (128x128B) | B 16KB (128x128B)
#define SMEM_TOTAL (STAGES * STAGE_BYTES)
#define NBAND 16

static __device__ __forceinline__ uint32_t smem_u32(const void* p) {
    uint32_t a;
    asm("{ .reg .u64 t; cvta.to.shared.u64 t, %1; cvt.u32.u64 %0, t; }" : "=r"(a) : "l"(p));
    return a;
}
static __device__ __forceinline__ void cp16(uint32_t dst, const void* src, uint32_t bytes) {
    asm volatile("cp.async.cg.shared.global [%0], [%1], 16, %2;" :: "r"(dst), "l"(src), "r"(bytes) : "memory");
}
#define CP_COMMIT() asm volatile("cp.async.commit_group;" ::: "memory")
#define CP_WAIT(n)  asm volatile("cp.async.wait_group %0;" :: "n"(n) : "memory")
#define LDSM4(r0, r1, r2, r3, a) \
    asm volatile("ldmatrix.sync.aligned.m8n8.x4.shared.b16 {%0,%1,%2,%3}, [%4];" \
        : "=r"(r0), "=r"(r1), "=r"(r2), "=r"(r3) : "r"(a))
#define MMA16816(c, a, b0, b1) \
    asm volatile("mma.sync.aligned.m16n8k16.row.col.f32.bf16.bf16.f32 " \
        "{%0,%1,%2,%3},{%4,%5,%6,%7},{%8,%9},{%0,%1,%2,%3};" \
        : "+f"((c)[0]), "+f"((c)[1]), "+f"((c)[2]), "+f"((c)[3]) \
        : "r"((a)[0]), "r"((a)[1]), "r"((a)[2]), "r"((a)[3]), "r"(b0), "r"(b1))

// ---------------- static device scratch ----------------
__device__ float g_S[(size_t)BATCH * NH];
__device__ float g_P[(size_t)BATCH * NH * KLR];
__device__ float g_t[(size_t)BATCH * NH];
__device__ __align__(1024) __nv_bfloat16 g_a2x[(size_t)BATCH * 2 * D_IN];    // x    [hi|lo]
__device__ __align__(1024) __nv_bfloat16 g_a2f[(size_t)BATCH * 2 * NH];      // feat [hi|lo]
__device__ __align__(1024) __nv_bfloat16 g_b2[(size_t)(NH * KLR + NH) * 2 * NH]; // [v | mu] rows, [hi|lo]
__device__ __align__(1024) __nv_bfloat16 g_b2l[(size_t)NCLS * 2 * NH];       // Wl [hi|lo]
__device__ float g_rowsq[BATCH];
__device__ float g_msq[NH];
__device__ float g_c[NH * KLR];
__device__ float g_mean[NH];
__device__ float g_scale[NH];
__device__ float g_shift[NH];
__device__ float g_psum[NSEG * NH];
__device__ float g_psq[NSEG * NH];

// ================= HMMA bf16 split GEMM (128x128 tile, merged output) =================
// Logical C[m,n] = sum over 3 segments: hiA*hiB + loA*hiB + hiA*loB.
// Physical: A2 (M, 2*Kd) = [hi|lo], B2 (Nrows, 2*Kd) = [hi|lo].
// Output routing: col <  Ncut -> Cp[m*Ncut + col]           (P region, no bias)
//                 col >= Ncut -> Cs[m*Ns + (col-Ncut)] +bias (S / plain region)
__global__ void __launch_bounds__(256)
gemm_mma(const __nv_bfloat16* __restrict__ A2, const __nv_bfloat16* __restrict__ B2,
         float* __restrict__ Cp, float* __restrict__ Cs,
         int Mt, int Ncut, int Ntot, int Ns, int Kd, const float* __restrict__ bias)
{
    extern __shared__ __align__(1024) char smem[];
    const uint32_t sbase = smem_u32(smem);
    const int tid = threadIdx.x;
    const int wid = tid >> 5;
    const int lane = tid & 31;
    const int wm = wid >> 2;          // 0..1  (m-warp, 64 rows)
    const int wn = wid & 3;           // 0..3  (n-warp, 32 cols)

    // banded raster: NBAND n-tiles per band; within band, n-fast for B reuse
    const int nt_total = (Ntot + 127) >> 7;
    const int per_band = Mt * NBAND;
    const int band = blockIdx.x / per_band;
    const int rem = blockIdx.x % per_band;
    const int n0t = band * NBAND;
    int nb = nt_total - n0t; if (nb > NBAND) nb = NBAND;
    const int mtile = rem / nb;
    const int ntile = n0t + rem % nb;
    const int row0 = mtile * 128;
    const int col0 = ntile * 128;
    const int nk1 = Kd >> 6;
    const int nk = 3 * nk1;
    const int Kd2 = 2 * Kd;

    float acc[4][4][4];
#pragma unroll
    for (int i = 0; i < 4; i++)
#pragma unroll
        for (int j = 0; j < 4; j++)
#pragma unroll
            for (int r = 0; r < 4; r++) acc[i][j][r] = 0.f;

    // ldmatrix lane geometry
    const int aRow = wm * 64 + (lane & 15);
    const int aK8 = (lane >> 4) * 8;
    const int bRow = wn * 32 + (lane & 7) + ((lane >> 4) & 1) * 8;
    const int bK8 = ((lane >> 3) & 1) * 8;

    auto issue = [&](int i) {
        if (i < nk) {
            const int s = i % STAGES;
            const uint32_t stA = sbase + s * STAGE_BYTES;
            const uint32_t stB = stA + 16384;
            const int ia = (i >= 2 * nk1) ? i - 2 * nk1 : i;
            const int ib = (i >= nk1) ? i - nk1 : i;
            const __nv_bfloat16* Ab = A2 + (size_t)row0 * Kd2 + (ia << 6);
            const __nv_bfloat16* Bb = B2 + (ib << 6);
#pragma unroll
            for (int it = 0; it < 4; it++) {
                int id = it * 256 + tid;
                int row = id >> 3, c = id & 7;
                uint32_t off = (uint32_t)(row * 128 + ((c * 16) ^ ((row & 7) << 4)));
                cp16(stA + off, Ab + (size_t)row * Kd2 + c * 8, 16);
            }
#pragma unroll
            for (int it = 0; it < 4; it++) {
                int id = it * 256 + tid;
                int row = id >> 3, c = id & 7;
                int gn = col0 + row;
                uint32_t bytes = (gn < Ntot) ? 16u : 0u;
                if (gn >= Ntot) gn = col0;
                uint32_t off = (uint32_t)(row * 128 + ((c * 16) ^ ((row & 7) << 4)));
                cp16(stB + off, Bb + (size_t)gn * Kd2 + c * 8, bytes);
            }
        }
        CP_COMMIT();
    };

#pragma unroll
    for (int i = 0; i < STAGES - 1; i++) issue(i);

    for (int i = 0; i < nk; i++) {
        CP_WAIT(STAGES - 2);
        __syncthreads();
        issue(i + STAGES - 1);            // prefetch early, overlap with compute
        const int s = i % STAGES;
        const uint32_t stA = sbase + s * STAGE_BYTES;
        const uint32_t stB = stA + 16384;
#pragma unroll
        for (int ks = 0; ks < 4; ks++) {
            uint32_t a[4][4], b[2][4];
            const int kc = ks * 16;
#pragma unroll
            for (int mi = 0; mi < 4; mi++) {
                int row = aRow + mi * 16;
                uint32_t off = (uint32_t)(row * 128 + (((kc + aK8) * 2) ^ ((row & 7) << 4)));
                LDSM4(a[mi][0], a[mi][1], a[mi][2], a[mi][3], stA + off);
            }
#pragma unroll
            for (int nbk = 0; nbk < 2; nbk++) {
                int row = bRow + nbk * 16;
                uint32_t off = (uint32_t)(row * 128 + (((kc + bK8) * 2) ^ ((row & 7) << 4)));
                LDSM4(b[nbk][0], b[nbk][1], b[nbk][2], b[nbk][3], stB + off);
            }
#pragma unroll
            for (int mi = 0; mi < 4; mi++)
#pragma unroll
                for (int ni = 0; ni < 4; ni++)
                    MMA16816(acc[mi][ni], a[mi], b[ni >> 1][(ni & 1) * 2], b[ni >> 1][(ni & 1) * 2 + 1]);
        }
    }

    // ---- epilogue: route P region vs S/plain region ----
#pragma unroll
    for (int mi = 0; mi < 4; mi++) {
        const int m = row0 + wm * 64 + mi * 16 + (lane >> 2);
#pragma unroll
        for (int ni = 0; ni < 4; ni++) {
            const int col = col0 + wn * 32 + ni * 8 + (lane & 3) * 2;
            float2 v0 = make_float2(acc[mi][ni][0], acc[mi][ni][1]);
            float2 v1 = make_float2(acc[mi][ni][2], acc[mi][ni][3]);
            if (col < Ncut) {
                *(float2*)(Cp + (size_t)m * Ncut + col) = v0;
                *(float2*)(Cp + (size_t)(m + 8) * Ncut + col) = v1;
            } else {
                int sc = col - Ncut;
                if (sc < Ns) {
                    if (bias) {
                        float b0 = bias[sc], b1 = bias[sc + 1];
                        v0.x += b0; v0.y += b1; v1.x += b0; v1.y += b1;
                    }
                    *(float2*)(Cs + (size_t)m * Ns + sc) = v0;
                    *(float2*)(Cs + (size_t)(m + 8) * Ns + sc) = v1;
                }
            }
        }
    }
}

// ---------------- split: fp32 -> [hi | lo] bf16 per row ----------------
__global__ void split2(const float* __restrict__ src, __nv_bfloat16* __restrict__ dst, int D) {
    size_t i = (size_t)blockIdx.x * 256 + threadIdx.x;
    size_t r = i / (size_t)D;
    int d = (int)(i - r * D);
    float x = src[i];
    __nv_bfloat16 h = __float2bfloat16(x);
    __nv_bfloat16 l = __float2bfloat16(x - __bfloat162float(h));
    __nv_bfloat16* o = dst + r * (size_t)(2 * D);
    o[d] = h; o[D + d] = l;
}

// ---------------- row sum of squares (fp32 source) ----------------
__global__ void rowsq_kernel(const float* __restrict__ x, float* __restrict__ out, int D) {
    int b = blockIdx.x;
    const float* p = x + (size_t)b * D;
    float s = 0.f;
    for (int i = threadIdx.x; i < D; i += 256) { float v = p[i]; s = fmaf(v, v, s); }
    __shared__ float red[256];
    red[threadIdx.x] = s;
    __syncthreads();
    for (int off = 128; off > 0; off >>= 1) {
        if (threadIdx.x < off) red[threadIdx.x] += red[threadIdx.x + off];
        __syncthreads();
    }
    if (threadIdx.x == 0) out[b] = red[0];
}

// ---------------- row sum of squares from [hi|lo] split rows ----------------
__global__ void rowsq_split(const __nv_bfloat16* __restrict__ f2, float* __restrict__ out, int D) {
    int b = blockIdx.x;
    const __nv_bfloat16* p = f2 + (size_t)b * 2 * D;
    float s = 0.f;
    for (int i = threadIdx.x; i < D; i += 256) {
        float v = __bfloat162float(p[i]) + __bfloat162float(p[D + i]);
        s = fmaf(v, v, s);
    }
    __shared__ float red[256];
    red[threadIdx.x] = s;
    __syncthreads();
    for (int off = 128; off > 0; off >>= 1) {
        if (threadIdx.x < off) red[threadIdx.x] += red[threadIdx.x + off];
        __syncthreads();
    }
    if (threadIdx.x == 0) out[b] = red[0];
}

// ---------------- per-n constants: msq, c ----------------
__global__ void prep_kernel(const float* __restrict__ mu, const float* __restrict__ v,
                            float* __restrict__ msq, float* __restrict__ c, int D) {
    int n = blockIdx.x;
    const float* mp = mu + (size_t)n * D;
    const float* vp = v + (size_t)n * KLR * D;
    float acc[5] = {0.f, 0.f, 0.f, 0.f, 0.f};
    for (int i = threadIdx.x; i < D; i += 256) {
        float m = mp[i];
        acc[0] = fmaf(m, m, acc[0]);
        acc[1] = fmaf(m, vp[i], acc[1]);
        acc[2] = fmaf(m, vp[(size_t)D + i], acc[2]);
        acc[3] = fmaf(m, vp[(size_t)2 * D + i], acc[3]);
        acc[4] = fmaf(m, vp[(size_t)3 * D + i], acc[4]);
    }
    __shared__ float red[256];
    for (int j = 0; j < 5; j++) {
        red[threadIdx.x] = acc[j];
        __syncthreads();
        for (int off = 128; off > 0; off >>= 1) {
            if (threadIdx.x < off) red[threadIdx.x] += red[threadIdx.x + off];
            __syncthreads();
        }
        if (threadIdx.x == 0) {
            if (j == 0) msq[n] = red[0];
            else        c[n * KLR + (j - 1)] = red[0];
        }
        __syncthreads();
    }
}

// ---------------- fused quad epilogue + BN partial sum ----------------
__global__ void quad_bnsum(const float* __restrict__ S, const float* __restrict__ P,
                           const float* __restrict__ rsq, const float* __restrict__ msq,
                           const float* __restrict__ c, const float* __restrict__ lam,
                           float* __restrict__ t, float* __restrict__ psum, int mode) {
    int n = blockIdx.x * 256 + threadIdx.x;
    int seg = blockIdx.y;
    const int rows = BATCH / NSEG;
    float lamn = lam[n];
    float msqn = msq[n];
    float4 cc = *(const float4*)(c + n * 4);
    float s = 0.f;
    size_t b0 = (size_t)seg * rows;
    for (int r = 0; r < rows; r++) {
        size_t b = b0 + r;
        size_t idx = b * NH + n;
        float q = lamn * (rsq[b] - 2.f * S[idx] + msqn);
        float4 p = *(const float4*)(P + idx * 4);
        float d0 = p.x - cc.x, d1 = p.y - cc.y, d2 = p.z - cc.z, d3 = p.w - cc.w;
        q += d0 * d0 + d1 * d1 + d2 * d2 + d3 * d3;
        float v = mode ? expf(-q * (1.0f / (float)NH)) : -q;
        t[idx] = v;
        s += v;
    }
    psum[seg * NH + n] = s;
}

// ---------------- BatchNorm (two-pass variance) ----------------
__global__ void bn_mean(const float* __restrict__ psum, float* __restrict__ mean) {
    int n = blockIdx.x * 256 + threadIdx.x;
    float s = 0.f;
    for (int i = 0; i < NSEG; i++) s += psum[i * NH + n];
    mean[n] = s * (1.0f / (float)BATCH);
}
__global__ void bn_var_partial(const float* __restrict__ t, const float* __restrict__ mean,
                               float* __restrict__ psq) {
    int n = blockIdx.x * 256 + threadIdx.x;
    int seg = blockIdx.y;
    const int rows = BATCH / NSEG;
    const float* p = t + (size_t)seg * rows * NH + n;
    float m = mean[n];
    float s = 0.f;
    for (int r = 0; r < rows; r++) { float d = p[(size_t)r * NH] - m; s = fmaf(d, d, s); }
    psq[seg * NH + n] = s;
}
__global__ void bn_finalize(const float* __restrict__ psq, const float* __restrict__ mean,
                            const float* __restrict__ g, const float* __restrict__ be,
                            float* __restrict__ scale, float* __restrict__ shift) {
    int n = blockIdx.x * 256 + threadIdx.x;
    float s = 0.f;
    for (int i = 0; i < NSEG; i++) s += psq[i * NH + n];
    float var = s * (1.0f / (float)BATCH);
    float rstd = rsqrtf(var + BN_EPS);
    float sc = g[n] * rstd;
    scale[n] = sc;
    shift[n] = be[n] - mean[n] * sc;
}
// applies BN (+optional relu), writes [hi|lo] bf16 pair rows + optional fp32 outputs
__global__ void bn_apply(const float* __restrict__ t, const float* __restrict__ scale,
                         const float* __restrict__ shift,
                         __nv_bfloat16* __restrict__ f2,
                         float* o1, float* o2, int relu) {
    size_t idx = (size_t)blockIdx.x * 256 + threadIdx.x;
    int n = (int)(idx & (NH - 1));
    size_t b = idx >> 11;
    float v = fmaf(t[idx], scale[n], shift[n]);
    if (relu) v = fmaxf(v, 0.f);
    __nv_bfloat16 h = __float2bfloat16(v);
    __nv_bfloat16 l = __float2bfloat16(v - __bfloat162float(h));
    __nv_bfloat16* o = f2 + b * (size_t)(2 * NH);
    o[n] = h; o[NH + n] = l;
    if (o1) o1[idx] = v;
    if (o2) o2[idx] = v;
}

// ---------------- host orchestration ----------------
extern "C" void kernel_launch(void* const* d_in, const int* in_sizes, int n_in,
                              void* d_out, int out_size) {
    const float* x    = (const float*)d_in[0];
    const float* mu1  = (const float*)d_in[1];
    const float* lam1 = (const float*)d_in[2];
    const float* v1   = (const float*)d_in[3];
    const float* g1   = (const float*)d_in[4];
    const float* b1   = (const float*)d_in[5];
    const float* mu2  = (const float*)d_in[6];
    const float* lam2 = (const float*)d_in[7];
    const float* v2   = (const float*)d_in[8];
    const float* g2   = (const float*)d_in[9];
    const float* b2   = (const float*)d_in[10];
    const float* Wl   = (const float*)d_in[11];
    const float* bl   = (const float*)d_in[12];

    float *pS, *pP, *pT, *pR, *pM, *pC, *pMean, *pScale, *pShift, *pPsum, *pPsq;
    __nv_bfloat16 *pA2x, *pA2f, *pB2, *pB2l;
    cudaGetSymbolAddress((void**)&pS, g_S);
    cudaGetSymbolAddress((void**)&pP, g_P);
    cudaGetSymbolAddress((void**)&pT, g_t);
    cudaGetSymbolAddress((void**)&pA2x, g_a2x);
    cudaGetSymbolAddress((void**)&pA2f, g_a2f);
    cudaGetSymbolAddress((void**)&pB2, g_b2);
    cudaGetSymbolAddress((void**)&pB2l, g_b2l);
    cudaGetSymbolAddress((void**)&pR, g_rowsq);
    cudaGetSymbolAddress((void**)&pM, g_msq);
    cudaGetSymbolAddress((void**)&pC, g_c);
    cudaGetSymbolAddress((void**)&pMean, g_mean);
    cudaGetSymbolAddress((void**)&pScale, g_scale);
    cudaGetSymbolAddress((void**)&pShift, g_shift);
    cudaGetSymbolAddress((void**)&pPsum, g_psum);
    cudaGetSymbolAddress((void**)&pPsq, g_psq);

    cudaFuncSetAttribute(gemm_mma, cudaFuncAttributeMaxDynamicSharedMemorySize, SMEM_TOTAL);

    const size_t LOGITS_SZ = (size_t)BATCH * NCLS;
    const size_t FEAT_SZ   = (size_t)BATCH * NH;
    float* out = (float*)d_out;
    size_t extra = ((size_t)out_size > LOGITS_SZ) ? ((size_t)out_size - LOGITS_SZ) / FEAT_SZ : 0;
    float* f1dst = (extra >= 1) ? out + LOGITS_SZ : nullptr;
    float* f2a   = (extra >= 2) ? out + LOGITS_SZ + FEAT_SZ : nullptr;
    float* f2b   = (extra >= 3) ? out + LOGITS_SZ + 2 * FEAT_SZ : nullptr;

    dim3 bn_grid(NH / 256, NSEG);
    const int elem_blocks = (int)(((size_t)BATCH * NH) / 256);
    const int Mt = BATCH / 128;         // 64
    const int NMERGED = NH * (KLR + 1); // 10240
    const int merged_grid = Mt * (NMERGED / 128);  // 5120

    // ---------- Layer 1 ----------
    split2<<<(BATCH * D_IN) / 256, 256>>>(x, pA2x, D_IN);
    split2<<<(NH * KLR * D_IN) / 256, 256>>>(v1, pB2, D_IN);
    split2<<<(NH * D_IN) / 256, 256>>>(mu1, pB2 + (size_t)(NH * KLR) * 2 * D_IN, D_IN);
    rowsq_kernel<<<BATCH, 256>>>(x, pR, D_IN);
    prep_kernel<<<NH, 256>>>(mu1, v1, pM, pC, D_IN);
    gemm_mma<<<merged_grid, 256, SMEM_TOTAL>>>(pA2x, pB2, pP, pS, Mt, NH * KLR, NMERGED, NH, D_IN, nullptr);
    quad_bnsum<<<bn_grid, 256>>>(pS, pP, pR, pM, pC, lam1, pT, pPsum, 0);
    bn_mean<<<NH / 256, 256>>>(pPsum, pMean);
    bn_var_partial<<<bn_grid, 256>>>(pT, pMean, pPsq);
    bn_finalize<<<NH / 256, 256>>>(pPsq, pMean, g1, b1, pScale, pShift);
    bn_apply<<<elem_blocks, 256>>>(pT, pScale, pShift, pA2f, f1dst, nullptr, 0);

    // ---------- Layer 2 ----------
    split2<<<(NH * KLR * NH) / 256, 256>>>(v2, pB2, NH);
    split2<<<(NH * NH) / 256, 256>>>(mu2, pB2 + (size_t)(NH * KLR) * 2 * NH, NH);
    rowsq_split<<<BATCH, 256>>>(pA2f, pR, NH);
    prep_kernel<<<NH, 256>>>(mu2, v2, pM, pC, NH);
    gemm_mma<<<merged_grid, 256, SMEM_TOTAL>>>(pA2f, pB2, pP, pS, Mt, NH * KLR, NMERGED, NH, NH, nullptr);
    quad_bnsum<<<bn_grid, 256>>>(pS, pP, pR, pM, pC, lam2, pT, pPsum, 1);
    bn_mean<<<NH / 256, 256>>>(pPsum, pMean);
    bn_var_partial<<<bn_grid, 256>>>(pT, pMean, pPsq);
    bn_finalize<<<NH / 256, 256>>>(pPsq, pMean, g2, b2, pScale, pShift);
    bn_apply<<<elem_blocks, 256>>>(pT, pScale, pShift, pA2f, f2a, f2b, 1);

    // ---------- Logits ----------
    split2<<<(NCLS * NH) / 256, 256>>>(Wl, pB2l, NH);
    gemm_mma<<<Mt * ((NCLS + 127) / 128), 256, SMEM_TOTAL>>>(pA2f, pB2l, nullptr, out, Mt, 0, NCLS, NCLS, NH, bl);
}

// round 6
// speedup vs baseline: 1.5347x; 1.3958x over previous
#include <cuda_runtime.h>
#include <cuda_fp16.h>
#include <cstdint>

// Problem constants
#define BATCH 8192
#define D_IN  1024
#define NH    2048
#define KLR   4
#define NCLS  1000
#define BN_EPS 1e-5f
#define NSEG  32

#define STAGES 3
#define STAGE_BYTES 32768           // A 16KB (128x128B) | B 16KB (128x128B)
#define SMEM_TOTAL (STAGES * STAGE_BYTES)

static __device__ __forceinline__ uint32_t smem_u32(const void* p) {
    uint32_t a;
    asm("{ .reg .u64 t; cvta.to.shared.u64 t, %1; cvt.u32.u64 %0, t; }" : "=r"(a) : "l"(p));
    return a;
}
static __device__ __forceinline__ void cp16(uint32_t dst, const void* src, uint32_t bytes) {
    asm volatile("cp.async.cg.shared.global [%0], [%1], 16, %2;" :: "r"(dst), "l"(src), "r"(bytes) : "memory");
}
#define CP_COMMIT() asm volatile("cp.async.commit_group;" ::: "memory")
#define CP_WAIT(n)  asm volatile("cp.async.wait_group %0;" :: "n"(n) : "memory")
#define LDSM4(r0, r1, r2, r3, a) \
    asm volatile("ldmatrix.sync.aligned.m8n8.x4.shared.b16 {%0,%1,%2,%3}, [%4];" \
        : "=r"(r0), "=r"(r1), "=r"(r2), "=r"(r3) : "r"(a))
#define MMA16816(c, a, b0, b1) \
    asm volatile("mma.sync.aligned.m16n8k16.row.col.f32.f16.f16.f32 " \
        "{%0,%1,%2,%3},{%4,%5,%6,%7},{%8,%9},{%0,%1,%2,%3};" \
        : "+f"((c)[0]), "+f"((c)[1]), "+f"((c)[2]), "+f"((c)[3]) \
        : "r"((a)[0]), "r"((a)[1]), "r"((a)[2]), "r"((a)[3]), "r"(b0), "r"(b1))

// ---------------- static device scratch ----------------
__device__ float g_S[(size_t)BATCH * NH];
__device__ float g_P[(size_t)BATCH * NH * KLR];
__device__ float g_t[(size_t)BATCH * NH];
__device__ __align__(1024) __half g_a2x[(size_t)BATCH * 2 * D_IN];        // x    [hi|lo] fp16
__device__ __align__(1024) __half g_a2f[(size_t)BATCH * 2 * NH];          // feat [hi|lo] fp16
__device__ __align__(1024) __half g_b1[(size_t)(NH * KLR + NH) * NH];     // [v | mu] rows, hi fp16
__device__ __align__(1024) __half g_b1l[(size_t)NCLS * NH];               // Wl hi fp16
__device__ float g_rowsq[BATCH];
__device__ float g_msq[NH];
__device__ float g_c[NH * KLR];
__device__ float g_mean[NH];
__device__ float g_scale[NH];
__device__ float g_shift[NH];
__device__ float g_psum[NSEG * NH];
__device__ float g_psq[NSEG * NH];

// ================= HMMA fp16 2-term split GEMM (128x128 tile, merged output) =================
// Logical C[m,n] = hiA*hiB + loA*hiB  (= (hiA+loA)*hiB, A ~22 mantissa bits).
// Physical: A2 (M, 2*Kd) = [hi|lo] fp16, B1 (Nrows, Kd) = hi fp16.
// K-loop: nk = 2*nk1 chunks; A chunk ia = i (sequential over [hi|lo]);
//         B chunk ib = i mod nk1 (loops twice).
// Output routing: col <  Ncut -> Cp[m*Ncut + col]            (P region, no bias)
//                 col >= Ncut -> Cs[m*Ns + (col-Ncut)] +bias  (S / plain region)
__global__ void __launch_bounds__(256)
gemm_mma(const __half* __restrict__ A2, const __half* __restrict__ B1,
         float* __restrict__ Cp, float* __restrict__ Cs,
         int Mt, int Ncut, int Ntot, int Ns, int Kd, const float* __restrict__ bias)
{
    extern __shared__ __align__(1024) char smem[];
    const uint32_t sbase = smem_u32(smem);
    const int tid = threadIdx.x;
    const int wid = tid >> 5;
    const int lane = tid & 31;
    const int wm = wid >> 2;          // 0..1  (m-warp, 64 rows)
    const int wn = wid & 3;           // 0..3  (n-warp, 32 cols)

    // banded raster: 8 n-tiles per band, n-fast within band (B reuse, A L2-resident)
    const int bw = Mt * 8;
    const int band = blockIdx.x / bw;
    const int rr = blockIdx.x % bw;
    const int mtile = rr >> 3;
    const int ntile = band * 8 + (rr & 7);
    const int row0 = mtile * 128;
    const int col0 = ntile * 128;
    const int nk1 = Kd >> 6;
    const int nk = 2 * nk1;
    const int Kd2 = 2 * Kd;

    float acc[4][4][4];
#pragma unroll
    for (int i = 0; i < 4; i++)
#pragma unroll
        for (int j = 0; j < 4; j++)
#pragma unroll
            for (int r = 0; r < 4; r++) acc[i][j][r] = 0.f;

    // ldmatrix lane geometry
    const int aRow = wm * 64 + (lane & 15);
    const int aK8 = (lane >> 4) * 8;
    const int bRow = wn * 32 + (lane & 7) + ((lane >> 4) & 1) * 8;
    const int bK8 = ((lane >> 3) & 1) * 8;

    auto issue = [&](int i) {
        if (i < nk) {
            const int s = i % STAGES;
            const uint32_t stA = sbase + s * STAGE_BYTES;
            const uint32_t stB = stA + 16384;
            const int ib = (i >= nk1) ? i - nk1 : i;
            const __half* Ab = A2 + (size_t)row0 * Kd2 + (i << 6);
            const __half* Bb = B1 + (ib << 6);
#pragma unroll
            for (int it = 0; it < 4; it++) {
                int id = it * 256 + tid;
                int row = id >> 3, c = id & 7;
                uint32_t off = (uint32_t)(row * 128 + ((c * 16) ^ ((row & 7) << 4)));
                cp16(stA + off, Ab + (size_t)row * Kd2 + c * 8, 16);
            }
#pragma unroll
            for (int it = 0; it < 4; it++) {
                int id = it * 256 + tid;
                int row = id >> 3, c = id & 7;
                int gn = col0 + row;
                uint32_t bytes = (gn < Ntot) ? 16u : 0u;
                if (gn >= Ntot) gn = col0;
                uint32_t off = (uint32_t)(row * 128 + ((c * 16) ^ ((row & 7) << 4)));
                cp16(stB + off, Bb + (size_t)gn * Kd + c * 8, bytes);
            }
        }
        CP_COMMIT();
    };

#pragma unroll
    for (int i = 0; i < STAGES - 1; i++) issue(i);

    for (int i = 0; i < nk; i++) {
        CP_WAIT(STAGES - 2);
        __syncthreads();
        const int s = i % STAGES;
        const uint32_t stA = sbase + s * STAGE_BYTES;
        const uint32_t stB = stA + 16384;
#pragma unroll
        for (int ks = 0; ks < 4; ks++) {
            uint32_t a[4][4], b[2][4];
            const int kc = ks * 16;
#pragma unroll
            for (int mi = 0; mi < 4; mi++) {
                int row = aRow + mi * 16;
                uint32_t off = (uint32_t)(row * 128 + (((kc + aK8) * 2) ^ ((row & 7) << 4)));
                LDSM4(a[mi][0], a[mi][1], a[mi][2], a[mi][3], stA + off);
            }
#pragma unroll
            for (int nbk = 0; nbk < 2; nbk++) {
                int row = bRow + nbk * 16;
                uint32_t off = (uint32_t)(row * 128 + (((kc + bK8) * 2) ^ ((row & 7) << 4)));
                LDSM4(b[nbk][0], b[nbk][1], b[nbk][2], b[nbk][3], stB + off);
            }
#pragma unroll
            for (int mi = 0; mi < 4; mi++)
#pragma unroll
                for (int ni = 0; ni < 4; ni++)
                    MMA16816(acc[mi][ni], a[mi], b[ni >> 1][(ni & 1) * 2], b[ni >> 1][(ni & 1) * 2 + 1]);
        }
        issue(i + STAGES - 1);
    }

    // ---- epilogue: route P region vs S/plain region ----
#pragma unroll
    for (int mi = 0; mi < 4; mi++) {
        const int m = row0 + wm * 64 + mi * 16 + (lane >> 2);
#pragma unroll
        for (int ni = 0; ni < 4; ni++) {
            const int col = col0 + wn * 32 + ni * 8 + (lane & 3) * 2;
            float2 v0 = make_float2(acc[mi][ni][0], acc[mi][ni][1]);
            float2 v1 = make_float2(acc[mi][ni][2], acc[mi][ni][3]);
            if (col < Ncut) {
                *(float2*)(Cp + (size_t)m * Ncut + col) = v0;
                *(float2*)(Cp + (size_t)(m + 8) * Ncut + col) = v1;
            } else {
                int sc = col - Ncut;
                if (sc < Ns) {
                    if (bias) {
                        float b0 = bias[sc], b1 = bias[sc + 1];
                        v0.x += b0; v0.y += b1; v1.x += b0; v1.y += b1;
                    }
                    *(float2*)(Cs + (size_t)m * Ns + sc) = v0;
                    *(float2*)(Cs + (size_t)(m + 8) * Ns + sc) = v1;
                }
            }
        }
    }
}

// ---------------- split: fp32 -> [hi | lo] fp16 per row (A operands) ----------------
__global__ void split2(const float* __restrict__ src, __half* __restrict__ dst, int D) {
    size_t i = (size_t)blockIdx.x * 256 + threadIdx.x;
    size_t r = i / (size_t)D;
    int d = (int)(i - r * D);
    float x = src[i];
    __half h = __float2half(x);
    __half l = __float2half(x - __half2float(h));
    __half* o = dst + r * (size_t)(2 * D);
    o[d] = h; o[D + d] = l;
}

// ---------------- cast: fp32 -> fp16 (B operands) ----------------
__global__ void castB(const float* __restrict__ src, __half* __restrict__ dst) {
    size_t i = (size_t)blockIdx.x * 256 + threadIdx.x;
    dst[i] = __float2half(src[i]);
}

// ---------------- row sum of squares (fp32 source) ----------------
__global__ void rowsq_kernel(const float* __restrict__ x, float* __restrict__ out, int D) {
    int b = blockIdx.x;
    const float* p = x + (size_t)b * D;
    float s = 0.f;
    for (int i = threadIdx.x; i < D; i += 256) { float v = p[i]; s = fmaf(v, v, s); }
    __shared__ float red[256];
    red[threadIdx.x] = s;
    __syncthreads();
    for (int off = 128; off > 0; off >>= 1) {
        if (threadIdx.x < off) red[threadIdx.x] += red[threadIdx.x + off];
        __syncthreads();
    }
    if (threadIdx.x == 0) out[b] = red[0];
}

// ---------------- row sum of squares from [hi|lo] fp16 split rows ----------------
__global__ void rowsq_split(const __half* __restrict__ f2, float* __restrict__ out, int D) {
    int b = blockIdx.x;
    const __half* p = f2 + (size_t)b * 2 * D;
    float s = 0.f;
    for (int i = threadIdx.x; i < D; i += 256) {
        float v = __half2float(p[i]) + __half2float(p[D + i]);
        s = fmaf(v, v, s);
    }
    __shared__ float red[256];
    red[threadIdx.x] = s;
    __syncthreads();
    for (int off = 128; off > 0; off >>= 1) {
        if (threadIdx.x < off) red[threadIdx.x] += red[threadIdx.x + off];
        __syncthreads();
    }
    if (threadIdx.x == 0) out[b] = red[0];
}

// ---------------- per-n constants: msq, c ----------------
__global__ void prep_kernel(const float* __restrict__ mu, const float* __restrict__ v,
                            float* __restrict__ msq, float* __restrict__ c, int D) {
    int n = blockIdx.x;
    const float* mp = mu + (size_t)n * D;
    const float* vp = v + (size_t)n * KLR * D;
    float acc[5] = {0.f, 0.f, 0.f, 0.f, 0.f};
    for (int i = threadIdx.x; i < D; i += 256) {
        float m = mp[i];
        acc[0] = fmaf(m, m, acc[0]);
        acc[1] = fmaf(m, vp[i], acc[1]);
        acc[2] = fmaf(m, vp[(size_t)D + i], acc[2]);
        acc[3] = fmaf(m, vp[(size_t)2 * D + i], acc[3]);
        acc[4] = fmaf(m, vp[(size_t)3 * D + i], acc[4]);
    }
    __shared__ float red[256];
    for (int j = 0; j < 5; j++) {
        red[threadIdx.x] = acc[j];
        __syncthreads();
        for (int off = 128; off > 0; off >>= 1) {
            if (threadIdx.x < off) red[threadIdx.x] += red[threadIdx.x + off];
            __syncthreads();
        }
        if (threadIdx.x == 0) {
            if (j == 0) msq[n] = red[0];
            else        c[n * KLR + (j - 1)] = red[0];
        }
        __syncthreads();
    }
}

// ---------------- fused quad epilogue + BN partial sum ----------------
__global__ void quad_bnsum(const float* __restrict__ S, const float* __restrict__ P,
                           const float* __restrict__ rsq, const float* __restrict__ msq,
                           const float* __restrict__ c, const float* __restrict__ lam,
                           float* __restrict__ t, float* __restrict__ psum, int mode) {
    int n = blockIdx.x * 256 + threadIdx.x;
    int seg = blockIdx.y;
    const int rows = BATCH / NSEG;
    float lamn = lam[n];
    float msqn = msq[n];
    float4 cc = *(const float4*)(c + n * 4);
    float s = 0.f;
    size_t b0 = (size_t)seg * rows;
    for (int r = 0; r < rows; r++) {
        size_t b = b0 + r;
        size_t idx = b * NH + n;
        float q = lamn * (rsq[b] - 2.f * S[idx] + msqn);
        float4 p = *(const float4*)(P + idx * 4);
        float d0 = p.x - cc.x, d1 = p.y - cc.y, d2 = p.z - cc.z, d3 = p.w - cc.w;
        q += d0 * d0 + d1 * d1 + d2 * d2 + d3 * d3;
        float v = mode ? expf(-q * (1.0f / (float)NH)) : -q;
        t[idx] = v;
        s += v;
    }
    psum[seg * NH + n] = s;
}

// ---------------- BatchNorm (two-pass variance) ----------------
__global__ void bn_mean(const float* __restrict__ psum, float* __restrict__ mean) {
    int n = blockIdx.x * 256 + threadIdx.x;
    float s = 0.f;
    for (int i = 0; i < NSEG; i++) s += psum[i * NH + n];
    mean[n] = s * (1.0f / (float)BATCH);
}
__global__ void bn_var_partial(const float* __restrict__ t, const float* __restrict__ mean,
                               float* __restrict__ psq) {
    int n = blockIdx.x * 256 + threadIdx.x;
    int seg = blockIdx.y;
    const int rows = BATCH / NSEG;
    const float* p = t + (size_t)seg * rows * NH + n;
    float m = mean[n];
    float s = 0.f;
    for (int r = 0; r < rows; r++) { float d = p[(size_t)r * NH] - m; s = fmaf(d, d, s); }
    psq[seg * NH + n] = s;
}
__global__ void bn_finalize(const float* __restrict__ psq, const float* __restrict__ mean,
                            const float* __restrict__ g, const float* __restrict__ be,
                            float* __restrict__ scale, float* __restrict__ shift) {
    int n = blockIdx.x * 256 + threadIdx.x;
    float s = 0.f;
    for (int i = 0; i < NSEG; i++) s += psq[i * NH + n];
    float var = s * (1.0f / (float)BATCH);
    float rstd = rsqrtf(var + BN_EPS);
    float sc = g[n] * rstd;
    scale[n] = sc;
    shift[n] = be[n] - mean[n] * sc;
}
// applies BN (+optional relu), writes [hi|lo] fp16 pair rows + optional fp32 outputs
__global__ void bn_apply(const float* __restrict__ t, const float* __restrict__ scale,
                         const float* __restrict__ shift,
                         __half* __restrict__ f2,
                         float* o1, float* o2, int relu) {
    size_t idx = (size_t)blockIdx.x * 256 + threadIdx.x;
    int n = (int)(idx & (NH - 1));
    size_t b = idx >> 11;
    float v = fmaf(t[idx], scale[n], shift[n]);
    if (relu) v = fmaxf(v, 0.f);
    __half h = __float2half(v);
    __half l = __float2half(v - __half2float(h));
    __half* o = f2 + b * (size_t)(2 * NH);
    o[n] = h; o[NH + n] = l;
    if (o1) o1[idx] = v;
    if (o2) o2[idx] = v;
}

// ---------------- host orchestration ----------------
extern "C" void kernel_launch(void* const* d_in, const int* in_sizes, int n_in,
                              void* d_out, int out_size) {
    const float* x    = (const float*)d_in[0];
    const float* mu1  = (const float*)d_in[1];
    const float* lam1 = (const float*)d_in[2];
    const float* v1   = (const float*)d_in[3];
    const float* g1   = (const float*)d_in[4];
    const float* b1   = (const float*)d_in[5];
    const float* mu2  = (const float*)d_in[6];
    const float* lam2 = (const float*)d_in[7];
    const float* v2   = (const float*)d_in[8];
    const float* g2   = (const float*)d_in[9];
    const float* b2   = (const float*)d_in[10];
    const float* Wl   = (const float*)d_in[11];
    const float* bl   = (const float*)d_in[12];

    float *pS, *pP, *pT, *pR, *pM, *pC, *pMean, *pScale, *pShift, *pPsum, *pPsq;
    __half *pA2x, *pA2f, *pB1, *pB1l;
    cudaGetSymbolAddress((void**)&pS, g_S);
    cudaGetSymbolAddress((void**)&pP, g_P);
    cudaGetSymbolAddress((void**)&pT, g_t);
    cudaGetSymbolAddress((void**)&pA2x, g_a2x);
    cudaGetSymbolAddress((void**)&pA2f, g_a2f);
    cudaGetSymbolAddress((void**)&pB1, g_b1);
    cudaGetSymbolAddress((void**)&pB1l, g_b1l);
    cudaGetSymbolAddress((void**)&pR, g_rowsq);
    cudaGetSymbolAddress((void**)&pM, g_msq);
    cudaGetSymbolAddress((void**)&pC, g_c);
    cudaGetSymbolAddress((void**)&pMean, g_mean);
    cudaGetSymbolAddress((void**)&pScale, g_scale);
    cudaGetSymbolAddress((void**)&pShift, g_shift);
    cudaGetSymbolAddress((void**)&pPsum, g_psum);
    cudaGetSymbolAddress((void**)&pPsq, g_psq);

    cudaFuncSetAttribute(gemm_mma, cudaFuncAttributeMaxDynamicSharedMemorySize, SMEM_TOTAL);

    const size_t LOGITS_SZ = (size_t)BATCH * NCLS;
    const size_t FEAT_SZ   = (size_t)BATCH * NH;
    float* out = (float*)d_out;
    size_t extra = ((size_t)out_size > LOGITS_SZ) ? ((size_t)out_size - LOGITS_SZ) / FEAT_SZ : 0;
    float* f1dst = (extra >= 1) ? out + LOGITS_SZ : nullptr;
    float* f2a   = (extra >= 2) ? out + LOGITS_SZ + FEAT_SZ : nullptr;
    float* f2b   = (extra >= 3) ? out + LOGITS_SZ + 2 * FEAT_SZ : nullptr;

    dim3 bn_grid(NH / 256, NSEG);
    const int elem_blocks = (int)(((size_t)BATCH * NH) / 256);
    const int Mt = BATCH / 128;         // 64
    const int NMERGED = NH * (KLR + 1); // 10240
    const int merged_grid = Mt * (NMERGED / 128);  // 5120

    // ---------- Layer 1 ----------
    split2<<<(BATCH * D_IN) / 256, 256>>>(x, pA2x, D_IN);
    castB<<<(NH * KLR * D_IN) / 256, 256>>>(v1, pB1);
    castB<<<(NH * D_IN) / 256, 256>>>(mu1, pB1 + (size_t)(NH * KLR) * D_IN);
    rowsq_kernel<<<BATCH, 256>>>(x, pR, D_IN);
    prep_kernel<<<NH, 256>>>(mu1, v1, pM, pC, D_IN);
    gemm_mma<<<merged_grid, 256, SMEM_TOTAL>>>(pA2x, pB1, pP, pS, Mt, NH * KLR, NMERGED, NH, D_IN, nullptr);
    quad_bnsum<<<bn_grid, 256>>>(pS, pP, pR, pM, pC, lam1, pT, pPsum, 0);
    bn_mean<<<NH / 256, 256>>>(pPsum, pMean);
    bn_var_partial<<<bn_grid, 256>>>(pT, pMean, pPsq);
    bn_finalize<<<NH / 256, 256>>>(pPsq, pMean, g1, b1, pScale, pShift);
    bn_apply<<<elem_blocks, 256>>>(pT, pScale, pShift, pA2f, f1dst, nullptr, 0);

    // ---------- Layer 2 ----------
    castB<<<(NH * KLR * NH) / 256, 256>>>(v2, pB1);
    castB<<<(NH * NH) / 256, 256>>>(mu2, pB1 + (size_t)(NH * KLR) * NH);
    rowsq_split<<<BATCH, 256>>>(pA2f, pR, NH);
    prep_kernel<<<NH, 256>>>(mu2, v2, pM, pC, NH);
    gemm_mma<<<merged_grid, 256, SMEM_TOTAL>>>(pA2f, pB1, pP, pS, Mt, NH * KLR, NMERGED, NH, NH, nullptr);
    quad_bnsum<<<bn_grid, 256>>>(pS, pP, pR, pM, pC, lam2, pT, pPsum, 1);
    bn_mean<<<NH / 256, 256>>>(pPsum, pMean);
    bn_var_partial<<<bn_grid, 256>>>(pT, pMean, pPsq);
    bn_finalize<<<NH / 256, 256>>>(pPsq, pMean, g2, b2, pScale, pShift);
    bn_apply<<<elem_blocks, 256>>>(pT, pScale, pShift, pA2f, f2a, f2b, 1);

    // ---------- Logits ----------
    castB<<<(NCLS * NH) / 256, 256>>>(Wl, pB1l);
    gemm_mma<<<Mt * ((NCLS + 127) / 128), 256, SMEM_TOTAL>>>(pA2f, pB1l, nullptr, out, Mt, 0, NCLS, NCLS, NH, bl);
}